// round 1
// baseline (speedup 1.0000x reference)
#include <cuda_runtime.h>
#include <math.h>

#define B_ 4
#define S_ 2048
#define DIN 2048
#define DOUT 2048
#define H_ 8
#define K_ 64
#define V_ 64
#define PCOLS (H_*K_ + H_*K_ + H_*V_ + H_)   // 1544
#define QOFF 0
#define KOFF (H_*K_)            // 512
#define VOFF (2*H_*K_)          // 1024
#define FOFF (2*H_*K_ + H_*V_)  // 1536
#define GROUPS 4

// Scratch (allocation-free: __device__ globals)
__device__ float g_proj[(size_t)B_*S_*PCOLS];              // 50.6 MB
__device__ float g_yp[(size_t)B_*H_*GROUPS*S_*V_];         // 67 MB
__device__ float g_ys[(size_t)B_*S_*H_*V_];                // 16.8 MB

// ---------------------------------------------------------------------------
// Generic fp32 SGEMM: C[M,N] = A[M,K] * B[K,N], row-major.
// BM=BN=128, BK=8, 256 threads, 8x8 microtile. M%128==0, K%8==0, N%4==0 assumed.
// ---------------------------------------------------------------------------
#define BM 128
#define BN 128
#define BK 8

__global__ __launch_bounds__(256, 2) void sgemm_kernel(
    const float* __restrict__ A, const float* __restrict__ Bm, float* __restrict__ C,
    int M, int N, int Kd)
{
    __shared__ float As[BK][BM];
    __shared__ float Bs[BK][BN];
    int tid = threadIdx.x;
    int bm = blockIdx.y * BM;
    int bn = blockIdx.x * BN;
    int aRow = tid >> 1;
    int aCol = (tid & 1) * 4;
    int bRow = tid >> 5;
    int bCol = (tid & 31) * 4;
    int tx = tid & 15, ty = tid >> 4;

    float acc[8][8];
#pragma unroll
    for (int i = 0; i < 8; i++)
#pragma unroll
        for (int j = 0; j < 8; j++) acc[i][j] = 0.f;

    const float* Aptr = A + (size_t)(bm + aRow) * Kd + aCol;

    for (int k0 = 0; k0 < Kd; k0 += BK) {
        float4 a = *(const float4*)(Aptr + k0);
        int gn = bn + bCol;
        float4 bv = make_float4(0.f, 0.f, 0.f, 0.f);
        if (gn < N) bv = *(const float4*)(Bm + (size_t)(k0 + bRow) * N + gn);
        As[aCol + 0][aRow] = a.x;
        As[aCol + 1][aRow] = a.y;
        As[aCol + 2][aRow] = a.z;
        As[aCol + 3][aRow] = a.w;
        *(float4*)&Bs[bRow][bCol] = bv;
        __syncthreads();
#pragma unroll
        for (int kk = 0; kk < BK; kk++) {
            float ar[8], br[8];
            *(float4*)&ar[0] = *(const float4*)&As[kk][ty * 8];
            *(float4*)&ar[4] = *(const float4*)&As[kk][ty * 8 + 4];
            *(float4*)&br[0] = *(const float4*)&Bs[kk][tx * 8];
            *(float4*)&br[4] = *(const float4*)&Bs[kk][tx * 8 + 4];
#pragma unroll
            for (int i = 0; i < 8; i++)
#pragma unroll
                for (int j = 0; j < 8; j++)
                    acc[i][j] = fmaf(ar[i], br[j], acc[i][j]);
        }
        __syncthreads();
    }
#pragma unroll
    for (int i = 0; i < 8; i++) {
        int row = bm + ty * 8 + i;
#pragma unroll
        for (int j = 0; j < 8; j += 4) {
            int col = bn + tx * 8 + j;
            if (col < N)
                *(float4*)&C[(size_t)row * N + col] =
                    make_float4(acc[i][j], acc[i][j + 1], acc[i][j + 2], acc[i][j + 3]);
        }
    }
}

// ---------------------------------------------------------------------------
// Scan kernel. Grid (GROUPS, H, B), 256 threads. Each warp owns 2 state rows
// (k-rows). W columns for lane l and l+32 live in registers (128 regs/lane).
// Per step: broadcast s through shared (float2 packs both rows), 256 FFMA
// matmul, forget-gate update + kv^T outer add, partial readout reduced across
// the block's 8 warps and written to g_yp. Final state goes to d_out tail.
// ---------------------------------------------------------------------------
__global__ __launch_bounds__(256, 1) void scan_kernel(
    const float* __restrict__ proj, const float* __restrict__ input_state,
    const float* __restrict__ state_w, float* __restrict__ yp,
    float* __restrict__ fs_out)
{
    __shared__ float2 ssh[8][64];
    __shared__ float yred[8][64];
    int tid = threadIdx.x;
    int w = tid >> 5;
    int l = tid & 31;
    int g = blockIdx.x;
    int h = blockIdx.y;
    int b = blockIdx.z;
    int r0 = g * 16 + w * 2;
    int r1 = r0 + 1;

    // Load this lane's two W columns into registers
    float wr0[64], wr1[64];
    const float* Wp = state_w + h * (V_ * V_);
#pragma unroll
    for (int v = 0; v < 64; v++) {
        wr0[v] = Wp[v * 64 + l];
        wr1[v] = Wp[v * 64 + l + 32];
    }

    // Initial state
    const float* isp = input_state + ((size_t)b * H_ + h) * (K_ * V_);
    float sA0 = isp[r0 * 64 + l], sA1 = isp[r0 * 64 + l + 32];
    float sB0 = isp[r1 * 64 + l], sB1 = isp[r1 * 64 + l + 32];

    // Prefetch t=0 inputs
    const float* p = proj + (size_t)(b * S_) * PCOLS;
    float qA = p[QOFF + h * 64 + r0], qB = p[QOFF + h * 64 + r1];
    float kA = p[KOFF + h * 64 + r0], kB = p[KOFF + h * 64 + r1];
    float v0 = p[VOFF + h * 64 + l],  v1 = p[VOFF + h * 64 + l + 32];
    float fr = p[FOFF + h];

    size_t ypbase = ((size_t)((b * H_ + h) * GROUPS + g)) * S_ * 64;

    for (int t = 0; t < S_; ++t) {
        ssh[w][l]      = make_float2(sA0, sB0);
        ssh[w][l + 32] = make_float2(sA1, sB1);
        __syncwarp();

        // Prefetch next step's inputs (hide L2 latency behind the matmul)
        int tn = (t + 1 < S_) ? (t + 1) : t;
        const float* pn = proj + (size_t)(b * S_ + tn) * PCOLS;
        float nqA = pn[QOFF + h * 64 + r0], nqB = pn[QOFF + h * 64 + r1];
        float nkA = pn[KOFF + h * 64 + r0], nkB = pn[KOFF + h * 64 + r1];
        float nv0 = pn[VOFF + h * 64 + l],  nv1 = pn[VOFF + h * 64 + l + 32];
        float nfr = pn[FOFF + h];

        float acc0 = 0.f, acc1 = 0.f, acc2 = 0.f, acc3 = 0.f;
#pragma unroll
        for (int v = 0; v < 64; v++) {
            float2 sp = ssh[w][v];
            acc0 = fmaf(sp.x, wr0[v], acc0);
            acc1 = fmaf(sp.x, wr1[v], acc1);
            acc2 = fmaf(sp.y, wr0[v], acc2);
            acc3 = fmaf(sp.y, wr1[v], acc3);
        }

        float f = 1.f / (1.f + __expf(-fr));
        sA0 = fmaf(kA, v0, f * acc0);
        sA1 = fmaf(kA, v1, f * acc1);
        sB0 = fmaf(kB, v0, f * acc2);
        sB1 = fmaf(kB, v1, f * acc3);

        // Partial readout for this warp's two rows
        yred[w][l]      = fmaf(qB, sB0, qA * sA0);
        yred[w][l + 32] = fmaf(qB, sB1, qA * sA1);
        __syncthreads();
        if (tid < 64) {
            float s = 0.f;
#pragma unroll
            for (int ww = 0; ww < 8; ww++) s += yred[ww][tid];
            yp[ypbase + (size_t)t * 64 + tid] = s;
        }
        __syncthreads();

        qA = nqA; qB = nqB; kA = nkA; kB = nkB;
        v0 = nv0; v1 = nv1; fr = nfr;
    }

    // Final state -> d_out tail: layout (B, H, K, V) flattened
    float* fs = fs_out + ((size_t)b * H_ + h) * (K_ * V_);
    fs[r0 * 64 + l]      = sA0;
    fs[r0 * 64 + l + 32] = sA1;
    fs[r1 * 64 + l]      = sB0;
    fs[r1 * 64 + l + 32] = sB1;
}

// ---------------------------------------------------------------------------
// Sum the 4 per-group y partials into ys[b*S + t][h*64 + v]
// ---------------------------------------------------------------------------
__global__ void reduce_kernel(const float* __restrict__ yp, float* __restrict__ ys)
{
    int idx = blockIdx.x * 256 + threadIdx.x;   // total B*S*H*V = 4194304
    int v  = idx & 63;
    int hh = (idx >> 6) & 7;
    int t  = (idx >> 9) & (S_ - 1);
    int b  = idx >> 20;
    size_t base = ((size_t)((b * H_ + hh) * GROUPS)) * S_ * 64 + (size_t)t * 64 + v;
    float s = 0.f;
#pragma unroll
    for (int gg = 0; gg < GROUPS; gg++) s += yp[base + (size_t)gg * (S_ * 64)];
    ys[idx] = s;
}

// ---------------------------------------------------------------------------
extern "C" void kernel_launch(void* const* d_in, const int* in_sizes, int n_in,
                              void* d_out, int out_size)
{
    const float* x           = (const float*)d_in[0];
    const float* input_state = (const float*)d_in[1];
    const float* w_in        = (const float*)d_in[2];
    const float* state_w     = (const float*)d_in[3];
    const float* w_out       = (const float*)d_in[4];
    float* out = (float*)d_out;

    float *proj_p, *yp_p, *ys_p;
    cudaGetSymbolAddress((void**)&proj_p, g_proj);
    cudaGetSymbolAddress((void**)&yp_p, g_yp);
    cudaGetSymbolAddress((void**)&ys_p, g_ys);

    // 1) proj = x @ w_in   (8192 x 1544 x 2048)
    dim3 g1((PCOLS + BN - 1) / BN, (B_ * S_) / BM);
    sgemm_kernel<<<g1, 256>>>(x, w_in, proj_p, B_ * S_, PCOLS, DIN);

    // 2) recurrent scan; writes y partials + final_state (tail of d_out)
    float* fs_out = out + (size_t)B_ * S_ * DOUT;
    scan_kernel<<<dim3(GROUPS, H_, B_), 256>>>(proj_p, input_state, state_w, yp_p, fs_out);

    // 3) sum k-group partials
    reduce_kernel<<<(B_ * S_ * H_ * V_) / 256, 256>>>(yp_p, ys_p);

    // 4) out = ys @ w_out  (8192 x 2048 x 512)
    dim3 g2(DOUT / BN, (B_ * S_) / BM);
    sgemm_kernel<<<g2, 256>>>(ys_p, w_out, out, B_ * S_, DOUT, H_ * V_);
}

// round 2
// speedup vs baseline: 1.0071x; 1.0071x over previous
#include <cuda_runtime.h>
#include <math.h>

#define B_ 4
#define S_ 2048
#define DIN 2048
#define DOUT 2048
#define H_ 8
#define K_ 64
#define V_ 64
#define PCOLS (H_*K_ + H_*K_ + H_*V_ + H_)   // 1544
#define QOFF 0
#define KOFF (H_*K_)            // 512
#define VOFF (2*H_*K_)          // 1024
#define FOFF (2*H_*K_ + H_*V_)  // 1536
#define GROUPS 4

// Scratch (allocation-free: __device__ globals)
__device__ float g_proj[(size_t)B_*S_*PCOLS];              // 50.6 MB
__device__ float g_yp[(size_t)B_*H_*GROUPS*S_*V_];         // 67 MB
__device__ float g_ys[(size_t)B_*S_*H_*V_];                // 16.8 MB

// ---------------------------------------------------------------------------
// Generic fp32 SGEMM: C[M,N] = A[M,K] * B[K,N], row-major.
// BM=BN=128, BK=8, 256 threads, 8x8 microtile. M%128==0, K%8==0, N%4==0 assumed.
// ---------------------------------------------------------------------------
#define BM 128
#define BN 128
#define BK 8

__global__ __launch_bounds__(256, 2) void sgemm_kernel(
    const float* __restrict__ A, const float* __restrict__ Bm, float* __restrict__ C,
    int M, int N, int Kd)
{
    __shared__ float As[BK][BM];
    __shared__ float Bs[BK][BN];
    int tid = threadIdx.x;
    int bm = blockIdx.y * BM;
    int bn = blockIdx.x * BN;
    int aRow = tid >> 1;
    int aCol = (tid & 1) * 4;
    int bRow = tid >> 5;
    int bCol = (tid & 31) * 4;
    int tx = tid & 15, ty = tid >> 4;

    float acc[8][8];
#pragma unroll
    for (int i = 0; i < 8; i++)
#pragma unroll
        for (int j = 0; j < 8; j++) acc[i][j] = 0.f;

    const float* Aptr = A + (size_t)(bm + aRow) * Kd + aCol;

    for (int k0 = 0; k0 < Kd; k0 += BK) {
        float4 a = *(const float4*)(Aptr + k0);
        int gn = bn + bCol;
        float4 bv = make_float4(0.f, 0.f, 0.f, 0.f);
        if (gn < N) bv = *(const float4*)(Bm + (size_t)(k0 + bRow) * N + gn);
        As[aCol + 0][aRow] = a.x;
        As[aCol + 1][aRow] = a.y;
        As[aCol + 2][aRow] = a.z;
        As[aCol + 3][aRow] = a.w;
        *(float4*)&Bs[bRow][bCol] = bv;
        __syncthreads();
#pragma unroll
        for (int kk = 0; kk < BK; kk++) {
            float ar[8], br[8];
            *(float4*)&ar[0] = *(const float4*)&As[kk][ty * 8];
            *(float4*)&ar[4] = *(const float4*)&As[kk][ty * 8 + 4];
            *(float4*)&br[0] = *(const float4*)&Bs[kk][tx * 8];
            *(float4*)&br[4] = *(const float4*)&Bs[kk][tx * 8 + 4];
#pragma unroll
            for (int i = 0; i < 8; i++)
#pragma unroll
                for (int j = 0; j < 8; j++)
                    acc[i][j] = fmaf(ar[i], br[j], acc[i][j]);
        }
        __syncthreads();
    }
#pragma unroll
    for (int i = 0; i < 8; i++) {
        int row = bm + ty * 8 + i;
#pragma unroll
        for (int j = 0; j < 8; j += 4) {
            int col = bn + tx * 8 + j;
            if (col < N)
                *(float4*)&C[(size_t)row * N + col] =
                    make_float4(acc[i][j], acc[i][j + 1], acc[i][j + 2], acc[i][j + 3]);
        }
    }
}

// ---------------------------------------------------------------------------
// Scan kernel. Grid (GROUPS, H, B), 256 threads. Each warp owns 2 state rows
// (k-rows). W columns for lane l and l+32 live in registers (128 regs/lane).
// Per step: broadcast s through shared (float2 packs both rows), 256 FFMA
// matmul, forget-gate update + kv^T outer add, partial readout reduced across
// the block's 8 warps and written to g_yp. Final state goes to d_out tail.
// ---------------------------------------------------------------------------
__global__ __launch_bounds__(256, 1) void scan_kernel(
    const float* __restrict__ proj, const float* __restrict__ input_state,
    const float* __restrict__ state_w, float* __restrict__ yp,
    float* __restrict__ fs_out)
{
    __shared__ float2 ssh[8][64];
    __shared__ float yred[8][64];
    int tid = threadIdx.x;
    int w = tid >> 5;
    int l = tid & 31;
    int g = blockIdx.x;
    int h = blockIdx.y;
    int b = blockIdx.z;
    int r0 = g * 16 + w * 2;
    int r1 = r0 + 1;

    // Load this lane's two W columns into registers
    float wr0[64], wr1[64];
    const float* Wp = state_w + h * (V_ * V_);
#pragma unroll
    for (int v = 0; v < 64; v++) {
        wr0[v] = Wp[v * 64 + l];
        wr1[v] = Wp[v * 64 + l + 32];
    }

    // Initial state
    const float* isp = input_state + ((size_t)b * H_ + h) * (K_ * V_);
    float sA0 = isp[r0 * 64 + l], sA1 = isp[r0 * 64 + l + 32];
    float sB0 = isp[r1 * 64 + l], sB1 = isp[r1 * 64 + l + 32];

    // Prefetch t=0 inputs
    const float* p = proj + (size_t)(b * S_) * PCOLS;
    float qA = p[QOFF + h * 64 + r0], qB = p[QOFF + h * 64 + r1];
    float kA = p[KOFF + h * 64 + r0], kB = p[KOFF + h * 64 + r1];
    float v0 = p[VOFF + h * 64 + l],  v1 = p[VOFF + h * 64 + l + 32];
    float fr = p[FOFF + h];

    size_t ypbase = ((size_t)((b * H_ + h) * GROUPS + g)) * S_ * 64;

    for (int t = 0; t < S_; ++t) {
        ssh[w][l]      = make_float2(sA0, sB0);
        ssh[w][l + 32] = make_float2(sA1, sB1);
        __syncwarp();

        // Prefetch next step's inputs (hide L2 latency behind the matmul)
        int tn = (t + 1 < S_) ? (t + 1) : t;
        const float* pn = proj + (size_t)(b * S_ + tn) * PCOLS;
        float nqA = pn[QOFF + h * 64 + r0], nqB = pn[QOFF + h * 64 + r1];
        float nkA = pn[KOFF + h * 64 + r0], nkB = pn[KOFF + h * 64 + r1];
        float nv0 = pn[VOFF + h * 64 + l],  nv1 = pn[VOFF + h * 64 + l + 32];
        float nfr = pn[FOFF + h];

        float acc0 = 0.f, acc1 = 0.f, acc2 = 0.f, acc3 = 0.f;
#pragma unroll
        for (int v = 0; v < 64; v++) {
            float2 sp = ssh[w][v];
            acc0 = fmaf(sp.x, wr0[v], acc0);
            acc1 = fmaf(sp.x, wr1[v], acc1);
            acc2 = fmaf(sp.y, wr0[v], acc2);
            acc3 = fmaf(sp.y, wr1[v], acc3);
        }

        float f = 1.f / (1.f + __expf(-fr));
        sA0 = fmaf(kA, v0, f * acc0);
        sA1 = fmaf(kA, v1, f * acc1);
        sB0 = fmaf(kB, v0, f * acc2);
        sB1 = fmaf(kB, v1, f * acc3);

        // Partial readout for this warp's two rows
        yred[w][l]      = fmaf(qB, sB0, qA * sA0);
        yred[w][l + 32] = fmaf(qB, sB1, qA * sA1);
        __syncthreads();
        if (tid < 64) {
            float s = 0.f;
#pragma unroll
            for (int ww = 0; ww < 8; ww++) s += yred[ww][tid];
            yp[ypbase + (size_t)t * 64 + tid] = s;
        }
        __syncthreads();

        qA = nqA; qB = nqB; kA = nkA; kB = nkB;
        v0 = nv0; v1 = nv1; fr = nfr;
    }

    // Final state -> d_out tail: layout (B, H, K, V) flattened
    float* fs = fs_out + ((size_t)b * H_ + h) * (K_ * V_);
    fs[r0 * 64 + l]      = sA0;
    fs[r0 * 64 + l + 32] = sA1;
    fs[r1 * 64 + l]      = sB0;
    fs[r1 * 64 + l + 32] = sB1;
}

// ---------------------------------------------------------------------------
// Sum the 4 per-group y partials into ys[b*S + t][h*64 + v]
// ---------------------------------------------------------------------------
__global__ void reduce_kernel(const float* __restrict__ yp, float* __restrict__ ys)
{
    int idx = blockIdx.x * 256 + threadIdx.x;   // total B*S*H*V = 4194304
    int v  = idx & 63;
    int hh = (idx >> 6) & 7;
    int t  = (idx >> 9) & (S_ - 1);
    int b  = idx >> 20;
    size_t base = ((size_t)((b * H_ + hh) * GROUPS)) * S_ * 64 + (size_t)t * 64 + v;
    float s = 0.f;
#pragma unroll
    for (int gg = 0; gg < GROUPS; gg++) s += yp[base + (size_t)gg * (S_ * 64)];
    ys[idx] = s;
}

// ---------------------------------------------------------------------------
extern "C" void kernel_launch(void* const* d_in, const int* in_sizes, int n_in,
                              void* d_out, int out_size)
{
    const float* x           = (const float*)d_in[0];
    const float* input_state = (const float*)d_in[1];
    const float* w_in        = (const float*)d_in[2];
    const float* state_w     = (const float*)d_in[3];
    const float* w_out       = (const float*)d_in[4];
    float* out = (float*)d_out;

    float *proj_p, *yp_p, *ys_p;
    cudaGetSymbolAddress((void**)&proj_p, g_proj);
    cudaGetSymbolAddress((void**)&yp_p, g_yp);
    cudaGetSymbolAddress((void**)&ys_p, g_ys);

    // 1) proj = x @ w_in   (8192 x 1544 x 2048)
    dim3 g1((PCOLS + BN - 1) / BN, (B_ * S_) / BM);
    sgemm_kernel<<<g1, 256>>>(x, w_in, proj_p, B_ * S_, PCOLS, DIN);

    // 2) recurrent scan; writes y partials + final_state (tail of d_out)
    float* fs_out = out + (size_t)B_ * S_ * DOUT;
    scan_kernel<<<dim3(GROUPS, H_, B_), 256>>>(proj_p, input_state, state_w, yp_p, fs_out);

    // 3) sum k-group partials
    reduce_kernel<<<(B_ * S_ * H_ * V_) / 256, 256>>>(yp_p, ys_p);

    // 4) out = ys @ w_out  (8192 x 2048 x 512)
    dim3 g2(DOUT / BN, (B_ * S_) / BM);
    sgemm_kernel<<<g2, 256>>>(ys_p, w_out, out, B_ * S_, DOUT, H_ * V_);
}